// round 5
// baseline (speedup 1.0000x reference)
#include <cuda_runtime.h>
#include <cuda_fp16.h>
#include <math.h>

#define NN    50000
#define EE    800000
#define TOT   (EE + NN)     // edges + self loops = 850000
#define FIN   15
#define H1DIM 256           // heads(4) * 64
#define HEADS 4
#define H2DIM 64

// ---------------- scratch (device globals; no allocations allowed) ----------
__device__ __half  g_h1h  [NN * H1DIM];  // layer1 features (fp16)   [N,4,64]
__device__ __half  g_acc1h[NN * H1DIM];  // layer1 msg accumulator (fp16 RED)
__device__ float   g_as1  [NN * HEADS];
__device__ float   g_ad1  [NN * HEADS];
__device__ float   g_z1   [NN * HEADS];
__device__ __half  g_h2h  [NN * H2DIM];  // layer2 features (fp16)
__device__ __half  g_acc2h[NN * H2DIM];  // layer2 msg accumulator (fp16 RED)
__device__ float   g_as2  [NN];
__device__ float   g_ad2  [NN];
__device__ float   g_z2   [NN];
__device__ float   g_wa1s [FIN * HEADS]; // W1 @ att_src1 (per head)  [15,4]
__device__ float   g_wa1d [FIN * HEADS];
__device__ float   g_wa2s [H1DIM];       // W2 @ att_src2             [256]
__device__ float   g_wa2d [H1DIM];
__device__ double  g_final[H2DIM];

// ---------------- helpers ---------------------------------------------------
__device__ __forceinline__ void redv4h2(void* p, unsigned r0, unsigned r1,
                                        unsigned r2, unsigned r3) {
    asm volatile("red.global.add.noftz.v4.f16x2 [%0], {%1, %2, %3, %4};"
                 :: "l"(p), "r"(r0), "r"(r1), "r"(r2), "r"(r3) : "memory");
}
__device__ __forceinline__ void redv2h2(void* p, unsigned r0, unsigned r1) {
    asm volatile("red.global.add.noftz.v2.f16x2 [%0], {%1, %2};"
                 :: "l"(p), "r"(r0), "r"(r1) : "memory");
}
__device__ __forceinline__ unsigned scaleh2(unsigned packed, float w) {
    __half2 h = *reinterpret_cast<__half2*>(&packed);
    float2 f = __half22float2(h);
    f.x *= w; f.y *= w;
    __half2 r = __float22half2_rn(f);
    return *reinterpret_cast<unsigned*>(&r);
}

// ---------------- kernels ---------------------------------------------------
// fold attention vectors into tiny per-input-dim weights; zero g_final
__global__ void k_pre(const float* __restrict__ W1, const float* __restrict__ as1,
                      const float* __restrict__ ad1, const float* __restrict__ W2,
                      const float* __restrict__ as2, const float* __restrict__ ad2) {
    int t = threadIdx.x;  // 256
    if (t < H2DIM) g_final[t] = 0.0;
    float s = 0.f, d = 0.f;
    for (int j = 0; j < 64; j++) {
        float w = W2[t * 64 + j];
        s = fmaf(w, as2[j], s);
        d = fmaf(w, ad2[j], d);
    }
    g_wa2s[t] = s; g_wa2d[t] = d;
    if (t < FIN * HEADS) {
        int k = t >> 2, h = t & 3;
        float a = 0.f, b = 0.f;
        for (int j = 0; j < 64; j++) {
            float w = W1[k * H1DIM + h * 64 + j];
            a = fmaf(w, as1[h * 64 + j], a);
            b = fmaf(w, ad1[h * 64 + j], b);
        }
        g_wa1s[t] = a; g_wa1d[t] = b;
    }
}

// h1 = x @ W1 (store fp16), attention logits, and zero acc1/z1
__global__ void k_gemm1(const float* __restrict__ x, const float* __restrict__ W1) {
    __shared__ float sW[FIN * H1DIM];
    __shared__ float sx[FIN];
    int t = threadIdx.x;  // 256
    for (int j = t; j < FIN * H1DIM; j += 256) sW[j] = W1[j];
    for (int n = blockIdx.x; n < NN; n += gridDim.x) {
        __syncthreads();
        if (t < FIN) sx[t] = x[n * FIN + t];
        __syncthreads();
        float h = 0.f;
#pragma unroll
        for (int k = 0; k < FIN; k++) h = fmaf(sx[k], sW[k * H1DIM + t], h);
        size_t o = (size_t)n * H1DIM + t;
        g_h1h[o]   = __float2half_rn(h);
        g_acc1h[o] = __float2half_rn(0.f);
        if (t < 4) g_z1[n * HEADS + t] = 0.f;
        if (t < 8) {
            int hh = t & 3;
            const float* wa = (t < 4) ? g_wa1s : g_wa1d;
            float a = 0.f;
#pragma unroll
            for (int k = 0; k < FIN; k++) a = fmaf(sx[k], wa[k * HEADS + hh], a);
            if (t < 4) g_as1[n * HEADS + hh] = a;
            else       g_ad1[n * HEADS + hh] = a;
        }
    }
}

// accumulate exp-weights + messages (layer 1): warp per edge, fp16 v4 RED.
// No max subtraction: softmax is shift-invariant and |logit| is O(5) here.
__global__ void k_acc1(const int* __restrict__ ei) {
    int gw = (blockIdx.x * blockDim.x + threadIdx.x) >> 5;
    int lane = threadIdx.x & 31;
    if (gw >= TOT) return;
    int s, d;
    if (gw < EE) { s = ei[gw]; d = ei[EE + gw]; }
    else         { s = d = gw - EE; }
    float wv = 0.f;
    if (lane < HEADS) {
        float e = g_as1[s * HEADS + lane] + g_ad1[d * HEADS + lane];
        e = e > 0.f ? e : 0.2f * e;
        wv = expf(e);
        atomicAdd(&g_z1[d * HEADS + lane], wv);
    }
    // lane covers halves [8*lane, 8*lane+8) -> head = lane>>3
    float w = __shfl_sync(0xffffffffu, wv, lane >> 3);
    const uint4* hp = (const uint4*)(g_h1h + (size_t)s * H1DIM);
    uint4 hv = hp[lane];
    unsigned r0 = scaleh2(hv.x, w);
    unsigned r1 = scaleh2(hv.y, w);
    unsigned r2 = scaleh2(hv.z, w);
    unsigned r3 = scaleh2(hv.w, w);
    redv4h2(g_acc1h + (size_t)d * H1DIM + 8 * lane, r0, r1, r2, r3);
}

// Fused: normalize + bias + ELU into smem tile, layer-2 logits, and
// h2 = act @ W2 (register-tiled 4 nodes x 4 cols / thread), fp16 stores,
// zero acc2/z2.  64-node tile, smem A stride 258 (bank-safe), persistent grid.
#define SA_STRIDE 258
__global__ void k_l2(const float* __restrict__ W2, const float* __restrict__ b1) {
    extern __shared__ float sm[];
    float* sW  = sm;                          // 16384 floats
    float* sA  = sm + H1DIM * H2DIM;          // 64 * 258 floats
    float* sWs = sA + 64 * SA_STRIDE;         // 256 floats
    float* sWd = sWs + H1DIM;                 // 256 floats
    int t = threadIdx.x;  // 256
    int cg = t & 15;       // col group: cols 4*cg..4*cg+3
    int ng = t >> 4;       // node slot:  nodes ng, ng+16, ng+32, ng+48
    for (int j = t; j < H1DIM * H2DIM; j += 256) sW[j] = W2[j];
    sWs[t] = g_wa2s[t];
    sWd[t] = g_wa2d[t];
    float bb = b1[t];
    const float4* sW4 = (const float4*)sW;
    for (int base = blockIdx.x * 64; base < NN; base += gridDim.x * 64) {
        __syncthreads();
        // phase A: normalize + ELU into sA
        for (int r = 0; r < 64; r++) {
            int n = base + r;
            float a = 0.f;
            if (n < NN) {
                float z = g_z1[n * HEADS + (t >> 6)];
                float v = __half2float(g_acc1h[(size_t)n * H1DIM + t]) / z + bb;
                a = v > 0.f ? v : expm1f(v);
            }
            sA[r * SA_STRIDE + t] = a;
        }
        __syncthreads();
        // phase A2: layer-2 logits (4 threads per node)
        {
            int node = t >> 2, l4 = t & 3;
            const float* arow = sA + node * SA_STRIDE;
            float ps = 0.f, pd = 0.f;
#pragma unroll 8
            for (int j = l4; j < H1DIM; j += 4) {
                float a = arow[j];
                ps = fmaf(a, sWs[j], ps);
                pd = fmaf(a, sWd[j], pd);
            }
            ps += __shfl_xor_sync(0xffffffffu, ps, 1);
            ps += __shfl_xor_sync(0xffffffffu, ps, 2);
            pd += __shfl_xor_sync(0xffffffffu, pd, 1);
            pd += __shfl_xor_sync(0xffffffffu, pd, 2);
            int n = base + node;
            if (l4 == 0 && n < NN) {
                g_as2[n] = ps;
                g_ad2[n] = pd;
                g_z2[n]  = 0.f;
            }
        }
        // phase B: gemm
        float4 acc0 = {0,0,0,0}, acc1 = {0,0,0,0}, acc2 = {0,0,0,0}, acc3 = {0,0,0,0};
        const float* a0 = sA + (ng     ) * SA_STRIDE;
        const float* a1 = sA + (ng + 16) * SA_STRIDE;
        const float* a2 = sA + (ng + 32) * SA_STRIDE;
        const float* a3 = sA + (ng + 48) * SA_STRIDE;
#pragma unroll 4
        for (int k = 0; k < H1DIM; k++) {
            float4 w = sW4[k * 16 + cg];
            float v0 = a0[k], v1 = a1[k], v2 = a2[k], v3 = a3[k];
            acc0.x = fmaf(v0, w.x, acc0.x); acc0.y = fmaf(v0, w.y, acc0.y);
            acc0.z = fmaf(v0, w.z, acc0.z); acc0.w = fmaf(v0, w.w, acc0.w);
            acc1.x = fmaf(v1, w.x, acc1.x); acc1.y = fmaf(v1, w.y, acc1.y);
            acc1.z = fmaf(v1, w.z, acc1.z); acc1.w = fmaf(v1, w.w, acc1.w);
            acc2.x = fmaf(v2, w.x, acc2.x); acc2.y = fmaf(v2, w.y, acc2.y);
            acc2.z = fmaf(v2, w.z, acc2.z); acc2.w = fmaf(v2, w.w, acc2.w);
            acc3.x = fmaf(v3, w.x, acc3.x); acc3.y = fmaf(v3, w.y, acc3.y);
            acc3.z = fmaf(v3, w.z, acc3.z); acc3.w = fmaf(v3, w.w, acc3.w);
        }
        float4 accs[4] = {acc0, acc1, acc2, acc3};
#pragma unroll
        for (int i = 0; i < 4; i++) {
            int n = base + ng + 16 * i;
            if (n < NN) {
                __half2* hp = (__half2*)(g_h2h   + (size_t)n * H2DIM + 4 * cg);
                __half2* ap = (__half2*)(g_acc2h + (size_t)n * H2DIM + 4 * cg);
                float4 v = accs[i];
                hp[0] = __floats2half2_rn(v.x, v.y);
                hp[1] = __floats2half2_rn(v.z, v.w);
                ap[0] = __floats2half2_rn(0.f, 0.f);
                ap[1] = __floats2half2_rn(0.f, 0.f);
            }
        }
    }
}

// accumulate (layer 2): 2 edges per warp (16 lanes each), v2 fp16 RED
__global__ void k_acc2(const int* __restrict__ ei) {
    int gw = (blockIdx.x * blockDim.x + threadIdx.x) >> 5;
    int lane = threadIdx.x & 31;
    int half = lane >> 4;       // which edge within warp
    int l16  = lane & 15;
    int e = gw * 2 + half;
    if (e >= TOT) return;
    int s, d;
    if (e < EE) { s = ei[e]; d = ei[EE + e]; }
    else        { s = d = e - EE; }
    float wv = 0.f;
    if (l16 == 0) {
        float ev = g_as2[s] + g_ad2[d];
        ev = ev > 0.f ? ev : 0.2f * ev;
        wv = expf(ev);
        atomicAdd(&g_z2[d], wv);
    }
    float w = __shfl_sync(0xffffffffu, wv, half << 4);
    const uint2* hp = (const uint2*)(g_h2h + (size_t)s * H2DIM);
    uint2 hv = hp[l16];
    unsigned r0 = scaleh2(hv.x, w);
    unsigned r1 = scaleh2(hv.y, w);
    redv2h2(g_acc2h + (size_t)d * H2DIM + 4 * l16, r0, r1);
}

// normalize + bias + mean over nodes (double accumulation)
__global__ void k_final(const float* __restrict__ b2) {
    int t = threadIdx.x;  // 256
    int col = t & 63, ns = t >> 6;
    double sum = 0.0;
    for (int n = blockIdx.x * 4 + ns; n < NN; n += gridDim.x * 4) {
        float v = __half2float(g_acc2h[(size_t)n * H2DIM + col]) / g_z2[n] + b2[col];
        sum += (double)v;
    }
    __shared__ double sd[256];
    sd[t] = sum;
    __syncthreads();
    if (t < 128) sd[t] += sd[t + 128];
    __syncthreads();
    if (t < 64) atomicAdd(&g_final[t], sd[t] + sd[t + 64]);
}

__global__ void k_out(float* __restrict__ out) {
    int t = threadIdx.x;
    if (t < H2DIM) out[t] = (float)(g_final[t] * (1.0 / (double)NN));
}

// ---------------- launch -----------------------------------------------------
extern "C" void kernel_launch(void* const* d_in, const int* in_sizes, int n_in,
                              void* d_out, int out_size) {
    const float* x   = (const float*)d_in[0];
    const int*   ei  = (const int*)d_in[1];   // jax demotes int64 -> int32
    const float* W1  = (const float*)d_in[2];
    const float* as1 = (const float*)d_in[3];
    const float* ad1 = (const float*)d_in[4];
    const float* b1  = (const float*)d_in[5];
    const float* W2  = (const float*)d_in[6];
    const float* as2 = (const float*)d_in[7];
    const float* ad2 = (const float*)d_in[8];
    const float* b2  = (const float*)d_in[9];
    float* out = (float*)d_out;

    (void)in_sizes; (void)n_in; (void)out_size;

    const int smem2 = (H1DIM * H2DIM + 64 * SA_STRIDE + 2 * H1DIM) * (int)sizeof(float);
    cudaFuncSetAttribute(k_l2, cudaFuncAttributeMaxDynamicSharedMemorySize, smem2);

    k_pre<<<1, 256>>>(W1, as1, ad1, W2, as2, ad2);
    k_gemm1<<<2048, 256>>>(x, W1);
    k_acc1<<<(TOT * 32 + 255) / 256, 256>>>(ei);
    k_l2<<<148, 256, smem2>>>(W2, b1);
    k_acc2<<<((TOT + 1) / 2 * 32 + 255) / 256, 256>>>(ei);
    k_final<<<512, 256>>>(b2);
    k_out<<<1, 64>>>(out);
}

// round 6
// speedup vs baseline: 1.2738x; 1.2738x over previous
#include <cuda_runtime.h>
#include <cuda_fp16.h>
#include <math.h>

#define NN    50000
#define EE    800000
#define TOT   (EE + NN)     // edges + self loops = 850000
#define FIN   15
#define H1DIM 256           // heads(4) * 64
#define HEADS 4
#define H2DIM 64

// ---------------- scratch (device globals; no allocations allowed) ----------
__device__ __half  g_h1h  [NN * H1DIM];  // layer1 features (fp16)   [N,4,64]
__device__ __half  g_acc1h[NN * H1DIM];  // layer1 msg accumulator (fp16 RED)
__device__ float   g_as1  [NN * HEADS];
__device__ float   g_ad1  [NN * HEADS];
__device__ float   g_z1   [NN * HEADS];
__device__ __half  g_h2h  [NN * H2DIM];  // layer2 features (fp16)
__device__ __half  g_acc2h[NN * H2DIM];  // layer2 msg accumulator (fp16 RED)
__device__ float   g_as2  [NN];
__device__ float   g_ad2  [NN];
__device__ float   g_z2   [NN];
__device__ float   g_wa1s [FIN * HEADS]; // W1 @ att_src1 (per head)  [15,4]
__device__ float   g_wa1d [FIN * HEADS];
__device__ float   g_wa2s [H1DIM];       // W2 @ att_src2             [256]
__device__ float   g_wa2d [H1DIM];
__device__ double  g_final[H2DIM];

// ---------------- helpers ---------------------------------------------------
__device__ __forceinline__ void redv4h2(void* p, unsigned r0, unsigned r1,
                                        unsigned r2, unsigned r3) {
    asm volatile("red.global.add.noftz.v4.f16x2 [%0], {%1, %2, %3, %4};"
                 :: "l"(p), "r"(r0), "r"(r1), "r"(r2), "r"(r3) : "memory");
}
__device__ __forceinline__ void redv2h2(void* p, unsigned r0, unsigned r1) {
    asm volatile("red.global.add.noftz.v2.f16x2 [%0], {%1, %2};"
                 :: "l"(p), "r"(r0), "r"(r1) : "memory");
}
__device__ __forceinline__ unsigned scaleh2(unsigned packed, float w) {
    __half2 h = *reinterpret_cast<__half2*>(&packed);
    float2 f = __half22float2(h);
    f.x *= w; f.y *= w;
    __half2 r = __float22half2_rn(f);
    return *reinterpret_cast<unsigned*>(&r);
}

// ---------------- kernels ---------------------------------------------------
// fold attention vectors into tiny per-input-dim weights; zero g_final
__global__ void k_pre(const float* __restrict__ W1, const float* __restrict__ as1,
                      const float* __restrict__ ad1, const float* __restrict__ W2,
                      const float* __restrict__ as2, const float* __restrict__ ad2) {
    int t = threadIdx.x;  // 256
    if (t < H2DIM) g_final[t] = 0.0;
    float s = 0.f, d = 0.f;
    for (int j = 0; j < 64; j++) {
        float w = W2[t * 64 + j];
        s = fmaf(w, as2[j], s);
        d = fmaf(w, ad2[j], d);
    }
    g_wa2s[t] = s; g_wa2d[t] = d;
    if (t < FIN * HEADS) {
        int k = t >> 2, h = t & 3;
        float a = 0.f, b = 0.f;
        for (int j = 0; j < 64; j++) {
            float w = W1[k * H1DIM + h * 64 + j];
            a = fmaf(w, as1[h * 64 + j], a);
            b = fmaf(w, ad1[h * 64 + j], b);
        }
        g_wa1s[t] = a; g_wa1d[t] = b;
    }
}

// h1 = x @ W1 (store fp16), attention logits, and zero acc1/z1
__global__ void k_gemm1(const float* __restrict__ x, const float* __restrict__ W1) {
    __shared__ float sW[FIN * H1DIM];
    __shared__ float sx[FIN];
    int t = threadIdx.x;  // 256
    for (int j = t; j < FIN * H1DIM; j += 256) sW[j] = W1[j];
    for (int n = blockIdx.x; n < NN; n += gridDim.x) {
        __syncthreads();
        if (t < FIN) sx[t] = x[n * FIN + t];
        __syncthreads();
        float h = 0.f;
#pragma unroll
        for (int k = 0; k < FIN; k++) h = fmaf(sx[k], sW[k * H1DIM + t], h);
        size_t o = (size_t)n * H1DIM + t;
        g_h1h[o]   = __float2half_rn(h);
        g_acc1h[o] = __float2half_rn(0.f);
        if (t < 4) g_z1[n * HEADS + t] = 0.f;
        if (t < 8) {
            int hh = t & 3;
            const float* wa = (t < 4) ? g_wa1s : g_wa1d;
            float a = 0.f;
#pragma unroll
            for (int k = 0; k < FIN; k++) a = fmaf(sx[k], wa[k * HEADS + hh], a);
            if (t < 4) g_as1[n * HEADS + hh] = a;
            else       g_ad1[n * HEADS + hh] = a;
        }
    }
}

// accumulate exp-weights + messages (layer 1): warp per edge, fp16 v4 RED.
// No max subtraction: softmax is shift-invariant and |logit| is O(5) here.
__global__ void k_acc1(const int* __restrict__ ei) {
    int gw = (blockIdx.x * blockDim.x + threadIdx.x) >> 5;
    int lane = threadIdx.x & 31;
    if (gw >= TOT) return;
    int s, d;
    if (gw < EE) { s = ei[gw]; d = ei[EE + gw]; }
    else         { s = d = gw - EE; }
    float wv = 0.f;
    if (lane < HEADS) {
        float e = g_as1[s * HEADS + lane] + g_ad1[d * HEADS + lane];
        e = e > 0.f ? e : 0.2f * e;
        wv = expf(e);
        atomicAdd(&g_z1[d * HEADS + lane], wv);
    }
    // lane covers halves [8*lane, 8*lane+8) -> head = lane>>3
    float w = __shfl_sync(0xffffffffu, wv, lane >> 3);
    const uint4* hp = (const uint4*)(g_h1h + (size_t)s * H1DIM);
    uint4 hv = hp[lane];
    unsigned r0 = scaleh2(hv.x, w);
    unsigned r1 = scaleh2(hv.y, w);
    unsigned r2 = scaleh2(hv.z, w);
    unsigned r3 = scaleh2(hv.w, w);
    redv4h2(g_acc1h + (size_t)d * H1DIM + 8 * lane, r0, r1, r2, r3);
}

// Fused: normalize + bias + ELU into smem tile, layer-2 logits, and
// h2 = act @ W2 (2 nodes x 4 cols / thread), fp16 stores, zero acc2/z2.
// 32-node tile, smem ~35KB static -> ~5 CTAs/SM.  W2 read via __ldg (cached).
#define SA_STRIDE 258
#define TILE 32
__global__ void __launch_bounds__(256) k_l2(const float* __restrict__ W2,
                                            const float* __restrict__ b1) {
    __shared__ float sA [TILE * SA_STRIDE];
    __shared__ float sWs[H1DIM];
    __shared__ float sWd[H1DIM];
    int t = threadIdx.x;  // 256
    int cg = t & 15;       // col group: cols 4*cg..4*cg+3
    int ng = t >> 4;       // node slots ng, ng+16
    sWs[t] = g_wa2s[t];
    sWd[t] = g_wa2d[t];
    float bb = b1[t];
    const float4* W2v4 = (const float4*)W2;
    int base = blockIdx.x * TILE;
    // phase A: normalize + ELU into sA
    __syncthreads();
#pragma unroll 4
    for (int r = 0; r < TILE; r++) {
        int n = base + r;
        float a = 0.f;
        if (n < NN) {
            float z = g_z1[n * HEADS + (t >> 6)];
            float v = __half2float(g_acc1h[(size_t)n * H1DIM + t]) / z + bb;
            a = v > 0.f ? v : expm1f(v);
        }
        sA[r * SA_STRIDE + t] = a;
    }
    __syncthreads();
    // phase A2: layer-2 logits (8 threads per node)
    {
        int node = t >> 3, l8 = t & 7;
        const float* arow = sA + node * SA_STRIDE;
        float ps = 0.f, pd = 0.f;
#pragma unroll 8
        for (int j = l8; j < H1DIM; j += 8) {
            float a = arow[j];
            ps = fmaf(a, sWs[j], ps);
            pd = fmaf(a, sWd[j], pd);
        }
        ps += __shfl_xor_sync(0xffffffffu, ps, 1);
        ps += __shfl_xor_sync(0xffffffffu, ps, 2);
        ps += __shfl_xor_sync(0xffffffffu, ps, 4);
        pd += __shfl_xor_sync(0xffffffffu, pd, 1);
        pd += __shfl_xor_sync(0xffffffffu, pd, 2);
        pd += __shfl_xor_sync(0xffffffffu, pd, 4);
        int n = base + node;
        if (l8 == 0 && n < NN) {
            g_as2[n] = ps;
            g_ad2[n] = pd;
            g_z2[n]  = 0.f;
        }
    }
    // phase B: gemm (W2 streamed through L1/L2 via __ldg)
    float4 acc0 = {0,0,0,0}, acc1 = {0,0,0,0};
    const float* a0 = sA + (ng     ) * SA_STRIDE;
    const float* a1 = sA + (ng + 16) * SA_STRIDE;
#pragma unroll 8
    for (int k = 0; k < H1DIM; k++) {
        float4 w = __ldg(&W2v4[k * 16 + cg]);
        float v0 = a0[k], v1 = a1[k];
        acc0.x = fmaf(v0, w.x, acc0.x); acc0.y = fmaf(v0, w.y, acc0.y);
        acc0.z = fmaf(v0, w.z, acc0.z); acc0.w = fmaf(v0, w.w, acc0.w);
        acc1.x = fmaf(v1, w.x, acc1.x); acc1.y = fmaf(v1, w.y, acc1.y);
        acc1.z = fmaf(v1, w.z, acc1.z); acc1.w = fmaf(v1, w.w, acc1.w);
    }
    float4 accs[2] = {acc0, acc1};
#pragma unroll
    for (int i = 0; i < 2; i++) {
        int n = base + ng + 16 * i;
        if (n < NN) {
            __half2* hp = (__half2*)(g_h2h   + (size_t)n * H2DIM + 4 * cg);
            __half2* ap = (__half2*)(g_acc2h + (size_t)n * H2DIM + 4 * cg);
            float4 v = accs[i];
            hp[0] = __floats2half2_rn(v.x, v.y);
            hp[1] = __floats2half2_rn(v.z, v.w);
            ap[0] = __floats2half2_rn(0.f, 0.f);
            ap[1] = __floats2half2_rn(0.f, 0.f);
        }
    }
}

// accumulate (layer 2): 2 edges per warp (16 lanes each), v2 fp16 RED
__global__ void k_acc2(const int* __restrict__ ei) {
    int gw = (blockIdx.x * blockDim.x + threadIdx.x) >> 5;
    int lane = threadIdx.x & 31;
    int half = lane >> 4;       // which edge within warp
    int l16  = lane & 15;
    int e = gw * 2 + half;
    if (e >= TOT) return;
    int s, d;
    if (e < EE) { s = ei[e]; d = ei[EE + e]; }
    else        { s = d = e - EE; }
    float wv = 0.f;
    if (l16 == 0) {
        float ev = g_as2[s] + g_ad2[d];
        ev = ev > 0.f ? ev : 0.2f * ev;
        wv = expf(ev);
        atomicAdd(&g_z2[d], wv);
    }
    float w = __shfl_sync(0xffffffffu, wv, half << 4);
    const uint2* hp = (const uint2*)(g_h2h + (size_t)s * H2DIM);
    uint2 hv = hp[l16];
    unsigned r0 = scaleh2(hv.x, w);
    unsigned r1 = scaleh2(hv.y, w);
    redv2h2(g_acc2h + (size_t)d * H2DIM + 4 * l16, r0, r1);
}

// normalize + bias + mean over nodes (double accumulation)
__global__ void k_final(const float* __restrict__ b2) {
    int t = threadIdx.x;  // 256
    int col = t & 63, ns = t >> 6;
    double sum = 0.0;
    for (int n = blockIdx.x * 4 + ns; n < NN; n += gridDim.x * 4) {
        float v = __half2float(g_acc2h[(size_t)n * H2DIM + col]) / g_z2[n] + b2[col];
        sum += (double)v;
    }
    __shared__ double sd[256];
    sd[t] = sum;
    __syncthreads();
    if (t < 128) sd[t] += sd[t + 128];
    __syncthreads();
    if (t < 64) atomicAdd(&g_final[t], sd[t] + sd[t + 64]);
}

__global__ void k_out(float* __restrict__ out) {
    int t = threadIdx.x;
    if (t < H2DIM) out[t] = (float)(g_final[t] * (1.0 / (double)NN));
}

// ---------------- launch -----------------------------------------------------
extern "C" void kernel_launch(void* const* d_in, const int* in_sizes, int n_in,
                              void* d_out, int out_size) {
    const float* x   = (const float*)d_in[0];
    const int*   ei  = (const int*)d_in[1];   // jax demotes int64 -> int32
    const float* W1  = (const float*)d_in[2];
    const float* as1 = (const float*)d_in[3];
    const float* ad1 = (const float*)d_in[4];
    const float* b1  = (const float*)d_in[5];
    const float* W2  = (const float*)d_in[6];
    const float* as2 = (const float*)d_in[7];
    const float* ad2 = (const float*)d_in[8];
    const float* b2  = (const float*)d_in[9];
    float* out = (float*)d_out;

    (void)in_sizes; (void)n_in; (void)out_size;

    k_pre<<<1, 256>>>(W1, as1, ad1, W2, as2, ad2);
    k_gemm1<<<2048, 256>>>(x, W1);
    k_acc1<<<(TOT * 32 + 255) / 256, 256>>>(ei);
    k_l2<<<(NN + TILE - 1) / TILE, 256>>>(W2, b1);
    k_acc2<<<((TOT + 1) / 2 * 32 + 255) / 256, 256>>>(ei);
    k_final<<<512, 256>>>(b2);
    k_out<<<1, 64>>>(out);
}

// round 7
// speedup vs baseline: 1.4361x; 1.1275x over previous
#include <cuda_runtime.h>
#include <cuda_fp16.h>
#include <math.h>

#define NN    50000
#define EE    800000
#define TOT   (EE + NN)     // edges + self loops = 850000
#define FIN   15
#define H1DIM 256           // heads(4) * 64
#define HEADS 4
#define H2DIM 64

// ---------------- scratch (device globals; no allocations allowed) ----------
__device__ __half  g_h1h  [NN * H1DIM];  // layer1 features (fp16)   [N,4,64]
__device__ __half  g_acc1h[NN * H1DIM];  // layer1 msg accumulator (fp16 RED)
__device__ float   g_as1  [NN * HEADS];
__device__ float   g_ad1  [NN * HEADS];
__device__ float   g_z1   [NN * HEADS];
__device__ __half  g_h2h  [NN * H2DIM];  // layer2 features (fp16)
__device__ __half  g_acc2h[NN * H2DIM];  // layer2 msg accumulator (fp16 RED)
__device__ float   g_as2  [NN];
__device__ float   g_ad2  [NN];
__device__ float   g_z2   [NN];
__device__ float   g_wa1s [FIN * HEADS]; // W1 @ att_src1 (per head)  [15,4]
__device__ float   g_wa1d [FIN * HEADS];
__device__ float   g_wa2s [H1DIM];       // W2 @ att_src2             [256]
__device__ float   g_wa2d [H1DIM];
__device__ double  g_final[H2DIM];

// ---------------- helpers ---------------------------------------------------
__device__ __forceinline__ void redv4h2(void* p, unsigned r0, unsigned r1,
                                        unsigned r2, unsigned r3) {
    asm volatile("red.global.add.noftz.v4.f16x2 [%0], {%1, %2, %3, %4};"
                 :: "l"(p), "r"(r0), "r"(r1), "r"(r2), "r"(r3) : "memory");
}
__device__ __forceinline__ unsigned scaleh2(unsigned packed, float w) {
    __half2 h = *reinterpret_cast<__half2*>(&packed);
    float2 f = __half22float2(h);
    f.x *= w; f.y *= w;
    __half2 r = __float22half2_rn(f);
    return *reinterpret_cast<unsigned*>(&r);
}

// ---------------- kernels ---------------------------------------------------
// fold attention vectors into tiny per-input-dim weights; zero g_final
__global__ void k_pre(const float* __restrict__ W1, const float* __restrict__ as1,
                      const float* __restrict__ ad1, const float* __restrict__ W2,
                      const float* __restrict__ as2, const float* __restrict__ ad2) {
    int t = threadIdx.x;  // 256
    if (t < H2DIM) g_final[t] = 0.0;
    float s = 0.f, d = 0.f;
    for (int j = 0; j < 64; j++) {
        float w = W2[t * 64 + j];
        s = fmaf(w, as2[j], s);
        d = fmaf(w, ad2[j], d);
    }
    g_wa2s[t] = s; g_wa2d[t] = d;
    if (t < FIN * HEADS) {
        int k = t >> 2, h = t & 3;
        float a = 0.f, b = 0.f;
        for (int j = 0; j < 64; j++) {
            float w = W1[k * H1DIM + h * 64 + j];
            a = fmaf(w, as1[h * 64 + j], a);
            b = fmaf(w, ad1[h * 64 + j], b);
        }
        g_wa1s[t] = a; g_wa1d[t] = b;
    }
}

// h1 = x @ W1 (store fp16 pairs), attention logits, zero acc1/z1 (vectorized)
__global__ void k_gemm1(const float* __restrict__ x, const float* __restrict__ W1) {
    __shared__ float sW[FIN * H1DIM];
    __shared__ float sx[FIN];
    int t = threadIdx.x;  // 256
    for (int j = t; j < FIN * H1DIM; j += 256) sW[j] = W1[j];
    const uint4 z4 = {0u, 0u, 0u, 0u};
    for (int n = blockIdx.x; n < NN; n += gridDim.x) {
        __syncthreads();
        if (t < FIN) sx[t] = x[n * FIN + t];
        __syncthreads();
        float h = 0.f;
#pragma unroll
        for (int k = 0; k < FIN; k++) h = fmaf(sx[k], sW[k * H1DIM + t], h);
        float hn = __shfl_down_sync(0xffffffffu, h, 1);
        if (!(t & 1))
            *(__half2*)(g_h1h + (size_t)n * H1DIM + t) = __floats2half2_rn(h, hn);
        if (t < 32) ((uint4*)(g_acc1h + (size_t)n * H1DIM))[t] = z4;
        if (t < 4) g_z1[n * HEADS + t] = 0.f;
        if (t < 8) {
            int hh = t & 3;
            const float* wa = (t < 4) ? g_wa1s : g_wa1d;
            float a = 0.f;
#pragma unroll
            for (int k = 0; k < FIN; k++) a = fmaf(sx[k], wa[k * HEADS + hh], a);
            if (t < 4) g_as1[n * HEADS + hh] = a;
            else       g_ad1[n * HEADS + hh] = a;
        }
    }
}

// accumulate exp-weights + messages (layer 1): warp per edge, fp16 v4 RED.
// No max subtraction: softmax is shift-invariant and |logit| is O(5) here.
__global__ void k_acc1(const int* __restrict__ ei) {
    int gw = (blockIdx.x * blockDim.x + threadIdx.x) >> 5;
    int lane = threadIdx.x & 31;
    if (gw >= TOT) return;
    int s, d;
    if (gw < EE) { s = ei[gw]; d = ei[EE + gw]; }
    else         { s = d = gw - EE; }
    float wv = 0.f;
    if (lane < HEADS) {
        float e = g_as1[s * HEADS + lane] + g_ad1[d * HEADS + lane];
        e = e > 0.f ? e : 0.2f * e;
        wv = expf(e);
        atomicAdd(&g_z1[d * HEADS + lane], wv);
    }
    // lane covers halves [8*lane, 8*lane+8) -> head = lane>>3
    float w = __shfl_sync(0xffffffffu, wv, lane >> 3);
    const uint4* hp = (const uint4*)(g_h1h + (size_t)s * H1DIM);
    uint4 hv = hp[lane];
    unsigned r0 = scaleh2(hv.x, w);
    unsigned r1 = scaleh2(hv.y, w);
    unsigned r2 = scaleh2(hv.z, w);
    unsigned r3 = scaleh2(hv.w, w);
    redv4h2(g_acc1h + (size_t)d * H1DIM + 8 * lane, r0, r1, r2, r3);
}

// Fused: normalize + bias + ELU into smem tile (warp-per-row uint4 loads),
// layer-2 logits, h2 = act @ W2 (float4 LDS, 2 nodes x 4 cols / thread),
// fp16 stores, zero acc2/z2.
#define SA_STRIDE 264
#define TILE 32
__global__ void __launch_bounds__(256) k_l2(const float* __restrict__ W2,
                                            const float* __restrict__ b1) {
    __shared__ float sA [TILE * SA_STRIDE];
    __shared__ float sWs[H1DIM];
    __shared__ float sWd[H1DIM];
    int t = threadIdx.x;  // 256
    int lane = t & 31, w = t >> 5;
    sWs[t] = g_wa2s[t];
    sWd[t] = g_wa2d[t];
    int base = blockIdx.x * TILE;
    // per-thread column constants for phase A: cols 8*lane .. 8*lane+7
    float4 b1v0 = __ldg((const float4*)(b1 + 8 * lane));
    float4 b1v1 = __ldg((const float4*)(b1 + 8 * lane + 4));
    // phase A: warp per row (4 rows per warp)
    for (int r = w; r < TILE; r += 8) {
        int n = base + r;
        float4 o0 = {0,0,0,0}, o1 = {0,0,0,0};
        if (n < NN) {
            uint4 hv = ((const uint4*)(g_acc1h + (size_t)n * H1DIM))[lane];
            float rz = 1.f / g_z1[n * HEADS + (lane >> 3)];
            float2 f0 = __half22float2(*(__half2*)&hv.x);
            float2 f1 = __half22float2(*(__half2*)&hv.y);
            float2 f2 = __half22float2(*(__half2*)&hv.z);
            float2 f3 = __half22float2(*(__half2*)&hv.w);
            o0.x = f0.x * rz + b1v0.x; o0.y = f0.y * rz + b1v0.y;
            o0.z = f1.x * rz + b1v0.z; o0.w = f1.y * rz + b1v0.w;
            o1.x = f2.x * rz + b1v1.x; o1.y = f2.y * rz + b1v1.y;
            o1.z = f3.x * rz + b1v1.z; o1.w = f3.y * rz + b1v1.w;
            o0.x = o0.x > 0.f ? o0.x : expm1f(o0.x);
            o0.y = o0.y > 0.f ? o0.y : expm1f(o0.y);
            o0.z = o0.z > 0.f ? o0.z : expm1f(o0.z);
            o0.w = o0.w > 0.f ? o0.w : expm1f(o0.w);
            o1.x = o1.x > 0.f ? o1.x : expm1f(o1.x);
            o1.y = o1.y > 0.f ? o1.y : expm1f(o1.y);
            o1.z = o1.z > 0.f ? o1.z : expm1f(o1.z);
            o1.w = o1.w > 0.f ? o1.w : expm1f(o1.w);
        }
        float4* sp = (float4*)(sA + r * SA_STRIDE + 8 * lane);
        sp[0] = o0;
        sp[1] = o1;
    }
    __syncthreads();
    // phase A2: layer-2 logits (8 threads per node; stride-264 rows => no conflicts)
    {
        int node = t >> 3, l8 = t & 7;
        const float* arow = sA + node * SA_STRIDE;
        float ps = 0.f, pd = 0.f;
#pragma unroll 8
        for (int j = l8; j < H1DIM; j += 8) {
            float a = arow[j];
            ps = fmaf(a, sWs[j], ps);
            pd = fmaf(a, sWd[j], pd);
        }
        ps += __shfl_xor_sync(0xffffffffu, ps, 1);
        ps += __shfl_xor_sync(0xffffffffu, ps, 2);
        ps += __shfl_xor_sync(0xffffffffu, ps, 4);
        pd += __shfl_xor_sync(0xffffffffu, pd, 1);
        pd += __shfl_xor_sync(0xffffffffu, pd, 2);
        pd += __shfl_xor_sync(0xffffffffu, pd, 4);
        int n = base + node;
        if (l8 == 0 && n < NN) {
            g_as2[n] = ps;
            g_ad2[n] = pd;
            g_z2[n]  = 0.f;
        }
    }
    // phase B: gemm, float4 smem reads, W2 via __ldg
    int cg = t & 15;       // cols 4*cg..4*cg+3
    int ng = t >> 4;       // node slots ng, ng+16
    const float4* W2v4 = (const float4*)W2;
    float4 acc0 = {0,0,0,0}, acc1 = {0,0,0,0};
    const float* a0 = sA + (ng     ) * SA_STRIDE;
    const float* a1 = sA + (ng + 16) * SA_STRIDE;
#pragma unroll 4
    for (int k = 0; k < H1DIM; k += 4) {
        float4 v0 = *(const float4*)(a0 + k);
        float4 v1 = *(const float4*)(a1 + k);
        float4 w0 = __ldg(&W2v4[(k + 0) * 16 + cg]);
        float4 w1 = __ldg(&W2v4[(k + 1) * 16 + cg]);
        float4 w2 = __ldg(&W2v4[(k + 2) * 16 + cg]);
        float4 w3 = __ldg(&W2v4[(k + 3) * 16 + cg]);
        acc0.x = fmaf(v0.x, w0.x, acc0.x); acc0.y = fmaf(v0.x, w0.y, acc0.y);
        acc0.z = fmaf(v0.x, w0.z, acc0.z); acc0.w = fmaf(v0.x, w0.w, acc0.w);
        acc1.x = fmaf(v1.x, w0.x, acc1.x); acc1.y = fmaf(v1.x, w0.y, acc1.y);
        acc1.z = fmaf(v1.x, w0.z, acc1.z); acc1.w = fmaf(v1.x, w0.w, acc1.w);
        acc0.x = fmaf(v0.y, w1.x, acc0.x); acc0.y = fmaf(v0.y, w1.y, acc0.y);
        acc0.z = fmaf(v0.y, w1.z, acc0.z); acc0.w = fmaf(v0.y, w1.w, acc0.w);
        acc1.x = fmaf(v1.y, w1.x, acc1.x); acc1.y = fmaf(v1.y, w1.y, acc1.y);
        acc1.z = fmaf(v1.y, w1.z, acc1.z); acc1.w = fmaf(v1.y, w1.w, acc1.w);
        acc0.x = fmaf(v0.z, w2.x, acc0.x); acc0.y = fmaf(v0.z, w2.y, acc0.y);
        acc0.z = fmaf(v0.z, w2.z, acc0.z); acc0.w = fmaf(v0.z, w2.w, acc0.w);
        acc1.x = fmaf(v1.z, w2.x, acc1.x); acc1.y = fmaf(v1.z, w2.y, acc1.y);
        acc1.z = fmaf(v1.z, w2.z, acc1.z); acc1.w = fmaf(v1.z, w2.w, acc1.w);
        acc0.x = fmaf(v0.w, w3.x, acc0.x); acc0.y = fmaf(v0.w, w3.y, acc0.y);
        acc0.z = fmaf(v0.w, w3.z, acc0.z); acc0.w = fmaf(v0.w, w3.w, acc0.w);
        acc1.x = fmaf(v1.w, w3.x, acc1.x); acc1.y = fmaf(v1.w, w3.y, acc1.y);
        acc1.z = fmaf(v1.w, w3.z, acc1.z); acc1.w = fmaf(v1.w, w3.w, acc1.w);
    }
    float4 accs[2] = {acc0, acc1};
#pragma unroll
    for (int i = 0; i < 2; i++) {
        int n = base + ng + 16 * i;
        if (n < NN) {
            __half2* hp = (__half2*)(g_h2h   + (size_t)n * H2DIM + 4 * cg);
            __half2* ap = (__half2*)(g_acc2h + (size_t)n * H2DIM + 4 * cg);
            float4 v = accs[i];
            hp[0] = __floats2half2_rn(v.x, v.y);
            hp[1] = __floats2half2_rn(v.z, v.w);
            ap[0] = __floats2half2_rn(0.f, 0.f);
            ap[1] = __floats2half2_rn(0.f, 0.f);
        }
    }
}

// accumulate (layer 2): 4 edges per warp (8 lanes each), v4 fp16 RED.
// TOT % 4 == 0, so a full warp is always valid when gw*4 < TOT.
__global__ void k_acc2(const int* __restrict__ ei) {
    int gw = (blockIdx.x * blockDim.x + threadIdx.x) >> 5;
    int lane = threadIdx.x & 31;
    int sub = lane >> 3, l8 = lane & 7;
    int e = gw * 4 + sub;
    if (e >= TOT) return;
    int s, d;
    if (e < EE) { s = ei[e]; d = ei[EE + e]; }
    else        { s = d = e - EE; }
    float wv = 0.f;
    if (l8 == 0) {
        float ev = g_as2[s] + g_ad2[d];
        ev = ev > 0.f ? ev : 0.2f * ev;
        wv = expf(ev);
        atomicAdd(&g_z2[d], wv);
    }
    float w = __shfl_sync(0xffffffffu, wv, sub << 3);
    uint4 hv = ((const uint4*)(g_h2h + (size_t)s * H2DIM))[l8];
    unsigned r0 = scaleh2(hv.x, w);
    unsigned r1 = scaleh2(hv.y, w);
    unsigned r2 = scaleh2(hv.z, w);
    unsigned r3 = scaleh2(hv.w, w);
    redv4h2(g_acc2h + (size_t)d * H2DIM + 8 * l8, r0, r1, r2, r3);
}

// normalize + mean over nodes (bias folded into k_out).  Warp handles 4 nodes
// per iter (8 lanes each, uint4 loads); block-level smem reduction.
__global__ void k_final() {
    int t = threadIdx.x;  // 256
    int lane = t & 31, w = t >> 5;
    int sub = lane >> 3, l8 = lane & 7;
    int gw = blockIdx.x * 8 + w;           // grid 148 -> 1184 warps
    double sum[8] = {0,0,0,0,0,0,0,0};
    for (int n = gw * 4 + sub; n < NN; n += 1184 * 4) {
        float rz = 1.f / g_z2[n];
        uint4 hv = ((const uint4*)(g_acc2h + (size_t)n * H2DIM))[l8];
        float2 f0 = __half22float2(*(__half2*)&hv.x);
        float2 f1 = __half22float2(*(__half2*)&hv.y);
        float2 f2 = __half22float2(*(__half2*)&hv.z);
        float2 f3 = __half22float2(*(__half2*)&hv.w);
        sum[0] += (double)(f0.x * rz); sum[1] += (double)(f0.y * rz);
        sum[2] += (double)(f1.x * rz); sum[3] += (double)(f1.y * rz);
        sum[4] += (double)(f2.x * rz); sum[5] += (double)(f2.y * rz);
        sum[6] += (double)(f3.x * rz); sum[7] += (double)(f3.y * rz);
    }
#pragma unroll
    for (int i = 0; i < 8; i++) {
        sum[i] += __shfl_xor_sync(0xffffffffu, sum[i], 8);
        sum[i] += __shfl_xor_sync(0xffffffffu, sum[i], 16);
    }
    __shared__ double sd[8 * 64];
    if (sub == 0) {
#pragma unroll
        for (int i = 0; i < 8; i++) sd[w * 64 + 8 * l8 + i] = sum[i];
    }
    __syncthreads();
    if (t < 64) {
        double tot = 0.0;
#pragma unroll
        for (int j = 0; j < 8; j++) tot += sd[j * 64 + t];
        atomicAdd(&g_final[t], tot);
    }
}

__global__ void k_out(float* __restrict__ out, const float* __restrict__ b2) {
    int t = threadIdx.x;
    if (t < H2DIM) out[t] = (float)(g_final[t] * (1.0 / (double)NN)) + b2[t];
}

// ---------------- launch -----------------------------------------------------
extern "C" void kernel_launch(void* const* d_in, const int* in_sizes, int n_in,
                              void* d_out, int out_size) {
    const float* x   = (const float*)d_in[0];
    const int*   ei  = (const int*)d_in[1];   // jax demotes int64 -> int32
    const float* W1  = (const float*)d_in[2];
    const float* as1 = (const float*)d_in[3];
    const float* ad1 = (const float*)d_in[4];
    const float* b1  = (const float*)d_in[5];
    const float* W2  = (const float*)d_in[6];
    const float* as2 = (const float*)d_in[7];
    const float* ad2 = (const float*)d_in[8];
    const float* b2  = (const float*)d_in[9];
    float* out = (float*)d_out;

    (void)in_sizes; (void)n_in; (void)out_size;

    k_pre<<<1, 256>>>(W1, as1, ad1, W2, as2, ad2);
    k_gemm1<<<2048, 256>>>(x, W1);
    k_acc1<<<(TOT * 32 + 255) / 256, 256>>>(ei);
    k_l2<<<(NN + TILE - 1) / TILE, 256>>>(W2, b1);
    k_acc2<<<(((TOT + 3) / 4) * 32 + 255) / 256, 256>>>(ei);
    k_final<<<148, 256>>>();
    k_out<<<1, 64>>>(out, b2);
}

// round 8
// speedup vs baseline: 1.6800x; 1.1698x over previous
#include <cuda_runtime.h>
#include <cuda_fp16.h>
#include <math.h>

#define NN    50000
#define EE    800000
#define TOT   (EE + NN)     // edges + self loops = 850000
#define FIN   15
#define H1DIM 256           // heads(4) * 64
#define HEADS 4
#define H2DIM 64

// ---------------- scratch (device globals; no allocations allowed) ----------
__device__ __half  g_h1h  [NN * H1DIM];  // layer1 features (fp16)   [N,4,64]
__device__ __half  g_acc1h[NN * H1DIM];  // layer1 msg accumulator (fp16 RED)
__device__ float   g_as1  [NN * HEADS];
__device__ float   g_ad1  [NN * HEADS];
__device__ float   g_z1   [NN * HEADS];
__device__ __half  g_h2h  [NN * H2DIM];  // layer2 features (fp16)
__device__ __half  g_acc2h[NN * H2DIM];  // layer2 msg accumulator (fp16 RED)
__device__ float   g_as2  [NN];
__device__ float   g_ad2  [NN];
__device__ float   g_z2   [NN];
__device__ float   g_wa1s [FIN * HEADS]; // W1 @ att_src1 (per head)  [15,4]
__device__ float   g_wa1d [FIN * HEADS];
__device__ float   g_wa2s [H1DIM];       // W2 @ att_src2             [256]
__device__ float   g_wa2d [H1DIM];
__device__ double  g_final[H2DIM];

// ---------------- helpers ---------------------------------------------------
__device__ __forceinline__ void redv4h2(void* p, unsigned r0, unsigned r1,
                                        unsigned r2, unsigned r3) {
    asm volatile("red.global.add.noftz.v4.f16x2 [%0], {%1, %2, %3, %4};"
                 :: "l"(p), "r"(r0), "r"(r1), "r"(r2), "r"(r3) : "memory");
}
__device__ __forceinline__ unsigned scaleh2(unsigned packed, float w) {
    __half2 h = *reinterpret_cast<__half2*>(&packed);
    float2 f = __half22float2(h);
    f.x *= w; f.y *= w;
    __half2 r = __float22half2_rn(f);
    return *reinterpret_cast<unsigned*>(&r);
}
__device__ __forceinline__ float elu1(float v) { return v > 0.f ? v : expm1f(v); }

// ---------------- kernels ---------------------------------------------------
// fold attention vectors into tiny per-input-dim weights; zero g_final
__global__ void k_pre(const float* __restrict__ W1, const float* __restrict__ as1,
                      const float* __restrict__ ad1, const float* __restrict__ W2,
                      const float* __restrict__ as2, const float* __restrict__ ad2) {
    int t = threadIdx.x;  // 256
    if (t < H2DIM) g_final[t] = 0.0;
    float s = 0.f, d = 0.f;
    for (int j = 0; j < 64; j++) {
        float w = W2[t * 64 + j];
        s = fmaf(w, as2[j], s);
        d = fmaf(w, ad2[j], d);
    }
    g_wa2s[t] = s; g_wa2d[t] = d;
    if (t < FIN * HEADS) {
        int k = t >> 2, h = t & 3;
        float a = 0.f, b = 0.f;
        for (int j = 0; j < 64; j++) {
            float w = W1[k * H1DIM + h * 64 + j];
            a = fmaf(w, as1[h * 64 + j], a);
            b = fmaf(w, ad1[h * 64 + j], b);
        }
        g_wa1s[t] = a; g_wa1d[t] = b;
    }
}

// h1 = x @ W1 (fp16 pair stores), logits, zero acc1/z1.  32-node tile/block.
#define G1TILE 32
__global__ void __launch_bounds__(256) k_gemm1(const float* __restrict__ x,
                                               const float* __restrict__ W1) {
    __shared__ float sW[FIN * H1DIM];
    __shared__ float sx[G1TILE * 16];
    int t = threadIdx.x;  // 256
    for (int j = t; j < FIN * H1DIM; j += 256) sW[j] = W1[j];
    int base = blockIdx.x * G1TILE;
    // stage x tile
    for (int j = t; j < G1TILE * FIN; j += 256) {
        int r = j / FIN, k = j - r * FIN;
        int n = base + r;
        sx[r * 16 + k] = (n < NN) ? x[n * FIN + k] : 0.f;
    }
    __syncthreads();
    float wcol[FIN];
#pragma unroll
    for (int k = 0; k < FIN; k++) wcol[k] = sW[k * H1DIM + t];
    const uint4 z4 = {0u, 0u, 0u, 0u};
    int nmax = NN - base;  // rows valid in this tile
#pragma unroll 4
    for (int r = 0; r < G1TILE; r++) {
        if (r >= nmax) break;
        int n = base + r;
        float h = 0.f;
#pragma unroll
        for (int k = 0; k < FIN; k++) h = fmaf(sx[r * 16 + k], wcol[k], h);
        float hn = __shfl_down_sync(0xffffffffu, h, 1);
        if (!(t & 1))
            *(__half2*)(g_h1h + (size_t)n * H1DIM + t) = __floats2half2_rn(h, hn);
    }
    // zero acc1h (32 nodes x 32 uint4) and z1
    for (int j = t; j < G1TILE * 32; j += 256) {
        int r = j >> 5;
        if (r < nmax) ((uint4*)(g_acc1h + (size_t)(base + r) * H1DIM))[j & 31] = z4;
    }
    if (t < G1TILE * 4) {
        int r = t >> 2;
        if (r < nmax) g_z1[(base + r) * HEADS + (t & 3)] = 0.f;
    }
    // logits: exactly 256 threads = 32 nodes x 8 (4 src + 4 dst)
    {
        int r = t >> 3, idx = t & 7, hh = idx & 3;
        if (r < nmax) {
            const float* wa = (idx < 4) ? g_wa1s : g_wa1d;
            float a = 0.f;
#pragma unroll
            for (int k = 0; k < FIN; k++) a = fmaf(sx[r * 16 + k], wa[k * HEADS + hh], a);
            int n = base + r;
            if (idx < 4) g_as1[n * HEADS + hh] = a;
            else         g_ad1[n * HEADS + hh] = a;
        }
    }
}

// accumulate exp-weights + messages (layer 1): warp per edge, fp16 v4 RED.
// No max subtraction: softmax is shift-invariant and |logit| is O(5) here.
__global__ void k_acc1(const int* __restrict__ ei) {
    int gw = (blockIdx.x * blockDim.x + threadIdx.x) >> 5;
    int lane = threadIdx.x & 31;
    if (gw >= TOT) return;
    int s, d;
    if (gw < EE) { s = ei[gw]; d = ei[EE + gw]; }
    else         { s = d = gw - EE; }
    float wv = 0.f;
    if (lane < HEADS) {
        float e = g_as1[s * HEADS + lane] + g_ad1[d * HEADS + lane];
        e = e > 0.f ? e : 0.2f * e;
        wv = expf(e);
        atomicAdd(&g_z1[d * HEADS + lane], wv);
    }
    // lane covers halves [8*lane, 8*lane+8) -> head = lane>>3
    float w = __shfl_sync(0xffffffffu, wv, lane >> 3);
    const uint4* hp = (const uint4*)(g_h1h + (size_t)s * H1DIM);
    uint4 hv = hp[lane];
    unsigned r0 = scaleh2(hv.x, w);
    unsigned r1 = scaleh2(hv.y, w);
    unsigned r2 = scaleh2(hv.z, w);
    unsigned r3 = scaleh2(hv.w, w);
    redv4h2(g_acc1h + (size_t)d * H1DIM + 8 * lane, r0, r1, r2, r3);
}

// Fused: normalize + bias + ELU into smem tile with layer-2 logits computed
// in-flight (warp reduction), then h2 = act @ W2 (4 nodes x 4 cols / thread).
#define SA_STRIDE 264
#define TILE 64
__global__ void __launch_bounds__(256) k_l2(const float* __restrict__ W2,
                                            const float* __restrict__ b1) {
    __shared__ float sA[TILE * SA_STRIDE];
    int t = threadIdx.x;  // 256
    int lane = t & 31, w = t >> 5;
    int base = blockIdx.x * TILE;
    // per-lane column constants (cols 8*lane .. 8*lane+7)
    float4 b1v0 = __ldg((const float4*)(b1 + 8 * lane));
    float4 b1v1 = __ldg((const float4*)(b1 + 8 * lane + 4));
    float4 ws0  = __ldg((const float4*)(g_wa2s + 8 * lane));
    float4 ws1  = __ldg((const float4*)(g_wa2s + 8 * lane + 4));
    float4 wd0  = __ldg((const float4*)(g_wa2d + 8 * lane));
    float4 wd1  = __ldg((const float4*)(g_wa2d + 8 * lane + 4));
    // phase A: warp per row (8 rows per warp); logits fused via warp reduction
    for (int r = w; r < TILE; r += 8) {
        int n = base + r;
        float4 o0 = {0,0,0,0}, o1 = {0,0,0,0};
        if (n < NN) {
            uint4 hv = ((const uint4*)(g_acc1h + (size_t)n * H1DIM))[lane];
            float rz = 1.f / g_z1[n * HEADS + (lane >> 3)];
            float2 f0 = __half22float2(*(__half2*)&hv.x);
            float2 f1 = __half22float2(*(__half2*)&hv.y);
            float2 f2 = __half22float2(*(__half2*)&hv.z);
            float2 f3 = __half22float2(*(__half2*)&hv.w);
            o0.x = elu1(f0.x * rz + b1v0.x); o0.y = elu1(f0.y * rz + b1v0.y);
            o0.z = elu1(f1.x * rz + b1v0.z); o0.w = elu1(f1.y * rz + b1v0.w);
            o1.x = elu1(f2.x * rz + b1v1.x); o1.y = elu1(f2.y * rz + b1v1.y);
            o1.z = elu1(f3.x * rz + b1v1.z); o1.w = elu1(f3.y * rz + b1v1.w);
        }
        float4* sp = (float4*)(sA + r * SA_STRIDE + 8 * lane);
        sp[0] = o0;
        sp[1] = o1;
        // fused layer-2 logits
        float ps = o0.x * ws0.x + o0.y * ws0.y + o0.z * ws0.z + o0.w * ws0.w
                 + o1.x * ws1.x + o1.y * ws1.y + o1.z * ws1.z + o1.w * ws1.w;
        float pd = o0.x * wd0.x + o0.y * wd0.y + o0.z * wd0.z + o0.w * wd0.w
                 + o1.x * wd1.x + o1.y * wd1.y + o1.z * wd1.z + o1.w * wd1.w;
#pragma unroll
        for (int o = 16; o; o >>= 1) {
            ps += __shfl_xor_sync(0xffffffffu, ps, o);
            pd += __shfl_xor_sync(0xffffffffu, pd, o);
        }
        if (lane == 0 && n < NN) {
            g_as2[n] = ps;
            g_ad2[n] = pd;
            g_z2[n]  = 0.f;
        }
    }
    __syncthreads();
    // phase B: gemm, 4 nodes x 4 cols per thread
    int cg = t & 15;       // cols 4*cg..4*cg+3
    int ng = t >> 4;       // node slots ng, ng+16, ng+32, ng+48
    const float4* W2v4 = (const float4*)W2;
    float4 acc0 = {0,0,0,0}, acc1 = {0,0,0,0}, acc2 = {0,0,0,0}, acc3 = {0,0,0,0};
    const float* a0 = sA + (ng     ) * SA_STRIDE;
    const float* a1 = sA + (ng + 16) * SA_STRIDE;
    const float* a2 = sA + (ng + 32) * SA_STRIDE;
    const float* a3 = sA + (ng + 48) * SA_STRIDE;
#pragma unroll 4
    for (int k = 0; k < H1DIM; k += 4) {
        float4 v0 = *(const float4*)(a0 + k);
        float4 v1 = *(const float4*)(a1 + k);
        float4 v2 = *(const float4*)(a2 + k);
        float4 v3 = *(const float4*)(a3 + k);
        float4 w0 = __ldg(&W2v4[(k + 0) * 16 + cg]);
        float4 w1 = __ldg(&W2v4[(k + 1) * 16 + cg]);
        float4 w2 = __ldg(&W2v4[(k + 2) * 16 + cg]);
        float4 w3 = __ldg(&W2v4[(k + 3) * 16 + cg]);
#define STEP(vv, ww) \
        acc0.x = fmaf(v0.vv, ww.x, acc0.x); acc0.y = fmaf(v0.vv, ww.y, acc0.y); \
        acc0.z = fmaf(v0.vv, ww.z, acc0.z); acc0.w = fmaf(v0.vv, ww.w, acc0.w); \
        acc1.x = fmaf(v1.vv, ww.x, acc1.x); acc1.y = fmaf(v1.vv, ww.y, acc1.y); \
        acc1.z = fmaf(v1.vv, ww.z, acc1.z); acc1.w = fmaf(v1.vv, ww.w, acc1.w); \
        acc2.x = fmaf(v2.vv, ww.x, acc2.x); acc2.y = fmaf(v2.vv, ww.y, acc2.y); \
        acc2.z = fmaf(v2.vv, ww.z, acc2.z); acc2.w = fmaf(v2.vv, ww.w, acc2.w); \
        acc3.x = fmaf(v3.vv, ww.x, acc3.x); acc3.y = fmaf(v3.vv, ww.y, acc3.y); \
        acc3.z = fmaf(v3.vv, ww.z, acc3.z); acc3.w = fmaf(v3.vv, ww.w, acc3.w);
        STEP(x, w0) STEP(y, w1) STEP(z, w2) STEP(w, w3)
#undef STEP
    }
    float4 accs[4] = {acc0, acc1, acc2, acc3};
#pragma unroll
    for (int i = 0; i < 4; i++) {
        int n = base + ng + 16 * i;
        if (n < NN) {
            __half2* hp = (__half2*)(g_h2h   + (size_t)n * H2DIM + 4 * cg);
            __half2* ap = (__half2*)(g_acc2h + (size_t)n * H2DIM + 4 * cg);
            float4 v = accs[i];
            hp[0] = __floats2half2_rn(v.x, v.y);
            hp[1] = __floats2half2_rn(v.z, v.w);
            ap[0] = __floats2half2_rn(0.f, 0.f);
            ap[1] = __floats2half2_rn(0.f, 0.f);
        }
    }
}

// accumulate (layer 2): 4 edges per warp (8 lanes each), v4 fp16 RED.
__global__ void k_acc2(const int* __restrict__ ei) {
    int gw = (blockIdx.x * blockDim.x + threadIdx.x) >> 5;
    int lane = threadIdx.x & 31;
    int sub = lane >> 3, l8 = lane & 7;
    int e = gw * 4 + sub;
    if (e >= TOT) return;
    int s, d;
    if (e < EE) { s = ei[e]; d = ei[EE + e]; }
    else        { s = d = e - EE; }
    float wv = 0.f;
    if (l8 == 0) {
        float ev = g_as2[s] + g_ad2[d];
        ev = ev > 0.f ? ev : 0.2f * ev;
        wv = expf(ev);
        atomicAdd(&g_z2[d], wv);
    }
    float w = __shfl_sync(0xffffffffu, wv, sub << 3);
    uint4 hv = ((const uint4*)(g_h2h + (size_t)s * H2DIM))[l8];
    unsigned r0 = scaleh2(hv.x, w);
    unsigned r1 = scaleh2(hv.y, w);
    unsigned r2 = scaleh2(hv.z, w);
    unsigned r3 = scaleh2(hv.w, w);
    redv4h2(g_acc2h + (size_t)d * H2DIM + 8 * l8, r0, r1, r2, r3);
}

// normalize + mean over nodes (bias folded into k_out).
__global__ void k_final() {
    int t = threadIdx.x;  // 256
    int lane = t & 31, w = t >> 5;
    int sub = lane >> 3, l8 = lane & 7;
    int gw = blockIdx.x * 8 + w;           // grid 148 -> 1184 warps
    double sum[8] = {0,0,0,0,0,0,0,0};
    for (int n = gw * 4 + sub; n < NN; n += 1184 * 4) {
        float rz = 1.f / g_z2[n];
        uint4 hv = ((const uint4*)(g_acc2h + (size_t)n * H2DIM))[l8];
        float2 f0 = __half22float2(*(__half2*)&hv.x);
        float2 f1 = __half22float2(*(__half2*)&hv.y);
        float2 f2 = __half22float2(*(__half2*)&hv.z);
        float2 f3 = __half22float2(*(__half2*)&hv.w);
        sum[0] += (double)(f0.x * rz); sum[1] += (double)(f0.y * rz);
        sum[2] += (double)(f1.x * rz); sum[3] += (double)(f1.y * rz);
        sum[4] += (double)(f2.x * rz); sum[5] += (double)(f2.y * rz);
        sum[6] += (double)(f3.x * rz); sum[7] += (double)(f3.y * rz);
    }
#pragma unroll
    for (int i = 0; i < 8; i++) {
        sum[i] += __shfl_xor_sync(0xffffffffu, sum[i], 8);
        sum[i] += __shfl_xor_sync(0xffffffffu, sum[i], 16);
    }
    __shared__ double sd[8 * 64];
    if (sub == 0) {
#pragma unroll
        for (int i = 0; i < 8; i++) sd[w * 64 + 8 * l8 + i] = sum[i];
    }
    __syncthreads();
    if (t < 64) {
        double tot = 0.0;
#pragma unroll
        for (int j = 0; j < 8; j++) tot += sd[j * 64 + t];
        atomicAdd(&g_final[t], tot);
    }
}

__global__ void k_out(float* __restrict__ out, const float* __restrict__ b2) {
    int t = threadIdx.x;
    if (t < H2DIM) out[t] = (float)(g_final[t] * (1.0 / (double)NN)) + b2[t];
}

// ---------------- launch -----------------------------------------------------
extern "C" void kernel_launch(void* const* d_in, const int* in_sizes, int n_in,
                              void* d_out, int out_size) {
    const float* x   = (const float*)d_in[0];
    const int*   ei  = (const int*)d_in[1];   // jax demotes int64 -> int32
    const float* W1  = (const float*)d_in[2];
    const float* as1 = (const float*)d_in[3];
    const float* ad1 = (const float*)d_in[4];
    const float* b1  = (const float*)d_in[5];
    const float* W2  = (const float*)d_in[6];
    const float* as2 = (const float*)d_in[7];
    const float* ad2 = (const float*)d_in[8];
    const float* b2  = (const float*)d_in[9];
    float* out = (float*)d_out;

    (void)in_sizes; (void)n_in; (void)out_size;

    k_pre<<<1, 256>>>(W1, as1, ad1, W2, as2, ad2);
    k_gemm1<<<(NN + G1TILE - 1) / G1TILE, 256>>>(x, W1);
    k_acc1<<<(TOT * 32 + 255) / 256, 256>>>(ei);
    k_l2<<<(NN + TILE - 1) / TILE, 256>>>(W2, b1);
    k_acc2<<<(((TOT + 3) / 4) * 32 + 255) / 256, 256>>>(ei);
    k_final<<<148, 256>>>();
    k_out<<<1, 64>>>(out, b2);
}